// round 15
// baseline (speedup 1.0000x reference)
#include <cuda_runtime.h>
#include <cuda_fp16.h>
#include <math.h>
#include <stdint.h>

// ---------------- problem constants ----------------
#define BS      2
#define NQ      40000
#define NV      40000
#define EMBED   256
#define HEADS   8
#define POINTS  4
#define HEAD_DIM 32
#define SH      200
#define SW      200
#define MROWS   (BS * NQ)      // 80000

// ---------------- device scratch ----------------
__device__ float  g_v   [(size_t)BS * NV * EMBED];       // projected value (fp32)
__device__ float  g_oa  [(size_t)BS * NQ * 96];          // fused [off(64) | attn(32)]
__device__ __half g_tmp [(size_t)BS * NQ * EMBED];       // sampled output (fp16)
__device__ float  g_boa [96];
// transposed weights: [N][K] fp16
__device__ __half g_Wv [256 * 256];
__device__ __half g_Wo [256 * 256];
__device__ __half g_Woa[ 96 * 256];

// ---------------- warp mma / ldmatrix helpers ----------------
__device__ __forceinline__ void mma_f16(float* d, const uint32_t* a, const uint32_t* b) {
    asm volatile(
        "mma.sync.aligned.m16n8k16.row.col.f32.f16.f16.f32 "
        "{%0,%1,%2,%3}, {%4,%5,%6,%7}, {%8,%9}, {%0,%1,%2,%3};"
        : "+f"(d[0]), "+f"(d[1]), "+f"(d[2]), "+f"(d[3])
        : "r"(a[0]), "r"(a[1]), "r"(a[2]), "r"(a[3]), "r"(b[0]), "r"(b[1]));
}
__device__ __forceinline__ void ldsm_x4(uint32_t& r0, uint32_t& r1, uint32_t& r2, uint32_t& r3,
                                        uint32_t addr) {
    asm volatile("ldmatrix.sync.aligned.m8n8.x4.shared.b16 {%0,%1,%2,%3}, [%4];"
                 : "=r"(r0), "=r"(r1), "=r"(r2), "=r"(r3) : "r"(addr));
}
__device__ __forceinline__ void ldsm_x2(uint32_t& r0, uint32_t& r1, uint32_t addr) {
    asm volatile("ldmatrix.sync.aligned.m8n8.x2.shared.b16 {%0,%1}, [%2];"
                 : "=r"(r0), "=r"(r1) : "r"(addr));
}
__device__ __forceinline__ uint32_t cvt_f16x2(float hi, float lo) {
    uint32_t r;
    asm("cvt.rn.f16x2.f32 %0, %1, %2;" : "=r"(r) : "f"(hi), "f"(lo));
    return r;
}

// ---------------- merged weight transpose to fp16 ----------------
__global__ void convert_all_kernel(const float* __restrict__ Wv, const float* __restrict__ Wo,
                                   const float* __restrict__ Woff, const float* __restrict__ boff,
                                   const float* __restrict__ Wattn, const float* __restrict__ battn,
                                   __half* __restrict__ dWv, __half* __restrict__ dWo,
                                   __half* __restrict__ dWoa, float* __restrict__ bcomb)
{
    int idx = blockIdx.x * 256 + threadIdx.x;
    if (idx < 65536) {
        int n = idx >> 8, k = idx & 255;
        dWv[idx] = __float2half_rn(Wv[k * 256 + n]);
    } else if (idx < 131072) {
        int j = idx - 65536;
        int n = j >> 8, k = j & 255;
        dWo[j] = __float2half_rn(Wo[k * 256 + n]);
    } else if (idx < 131072 + 24576) {
        int j = idx - 131072;
        int n = j >> 8, k = j & 255;
        float v = (n < 64) ? Woff[k * 64 + n] : Wattn[k * 32 + (n - 64)];
        dWoa[j] = __float2half_rn(v);
        if (j < 96) bcomb[j] = (j < 64) ? boff[j] : battn[j - 64];
    }
}

// ---------------- fp16 HMMA GEMM: BM=64, 8 warps, warp tile 32 x BN/4 ----------------
// 3 CTAs/SM target. AT = float (cvt fill) or __half (copy fill).
template<int BN, bool RES, typename AT>
__global__ void __launch_bounds__(256, 3)
mma_gemm_kernel(const AT* __restrict__ A,
                const __half* __restrict__ Bt,
                const float* __restrict__ bias,
                const float* __restrict__ res,
                float* __restrict__ C, int ldC)
{
    constexpr int K = 256, BK = 128, BM = 64;
    constexpr int WN  = 4;
    constexpr int WTN = BN / WN;           // 32 or 24 cols per warp
    constexpr int MT  = 2;                 // 32 rows per warp / 16
    constexpr int NTI = WTN / 8;           // 4 or 3
    constexpr int NPAIR = NTI / 2;
    constexpr int AST = 272;               // bytes per 128-fp16 row (256 + 16 pad)
    constexpr int A_0 = 0;
    constexpr int B_0 = BM * AST;

    extern __shared__ char sm[];
    const uint32_t smBase = (uint32_t)__cvta_generic_to_shared(sm);

    const int tid  = threadIdx.x;
    const int wid  = tid >> 5;
    const int lane = tid & 31;
    const int g    = lane >> 2;
    const int c    = lane & 3;
    const int wm   = wid / WN;             // 0..1
    const int wn   = wid % WN;
    const int wmBase = wm * 32;
    const int wnBase = wn * WTN;
    const int bm   = blockIdx.y;
    const int nOff = blockIdx.x * BN;

    float acc[MT][NTI][4];
#pragma unroll
    for (int i = 0; i < MT; i++)
#pragma unroll
        for (int j = 0; j < NTI; j++)
#pragma unroll
            for (int q = 0; q < 4; q++) acc[i][j][q] = 0.f;

    const int aRow = wmBase + (lane & 15);
    const int aKs  = (lane >> 4) * 16;
    const int bRow = wnBase + ((lane >> 4) << 3) + (lane & 7);
    const int bKs  = ((lane >> 3) & 1) * 16;
    const uint32_t aB = smBase + (uint32_t)(A_0 + aRow * AST + aKs);
    const uint32_t bB = smBase + (uint32_t)(B_0 + bRow * AST + bKs);

    for (int it = 0; it < K / BK; it++) {
        const int k0 = it * BK;
        // ---- fill A tile: 64 rows x 128 cols ----
        if constexpr (sizeof(AT) == 4) {
#pragma unroll
            for (int f = tid; f < BM * 32; f += 256) {
                const int r = f >> 5, c4 = f & 31;
                float4 a = *reinterpret_cast<const float4*>(
                    &A[(size_t)(bm * BM + r) * K + k0 + c4 * 4]);
                uint2 v;
                v.x = cvt_f16x2(a.y, a.x);
                v.y = cvt_f16x2(a.w, a.z);
                *reinterpret_cast<uint2*>(sm + A_0 + r * AST + c4 * 8) = v;
            }
        } else {
#pragma unroll
            for (int f = tid; f < BM * 16; f += 256) {
                const int r = f >> 4, cu = f & 15;
                uint4 w = *reinterpret_cast<const uint4*>(
                    &A[(size_t)(bm * BM + r) * K + k0 + cu * 8]);
                *reinterpret_cast<uint4*>(sm + A_0 + r * AST + cu * 16) = w;
            }
        }
        // ---- fill B tile: BN rows x 128 fp16, 16B copies ----
#pragma unroll
        for (int f = tid; f < BN * 16; f += 256) {
            const int n = f >> 4, cu = f & 15;
            uint4 w = *reinterpret_cast<const uint4*>(&Bt[(nOff + n) * K + k0 + cu * 8]);
            *reinterpret_cast<uint4*>(sm + B_0 + n * AST + cu * 16) = w;
        }
        __syncthreads();

#pragma unroll
        for (int ks = 0; ks < BK / 16; ks++) {
            const uint32_t kb = ks * 32;
            uint32_t af[MT][4], bf[NTI][2];
#pragma unroll
            for (int p = 0; p < NPAIR; p++)
                ldsm_x4(bf[2*p][0], bf[2*p][1], bf[2*p+1][0], bf[2*p+1][1],
                        bB + (uint32_t)(p * 16 * AST) + kb);
            if (NTI & 1)
                ldsm_x2(bf[NTI-1][0], bf[NTI-1][1],
                        bB + (uint32_t)((NTI-1) * 8 * AST) + kb);
#pragma unroll
            for (int mi = 0; mi < MT; mi++)
                ldsm_x4(af[mi][0], af[mi][1], af[mi][2], af[mi][3],
                        aB + (uint32_t)(mi * 16 * AST) + kb);
#pragma unroll
            for (int mi = 0; mi < MT; mi++)
#pragma unroll
                for (int ni = 0; ni < NTI; ni++)
                    mma_f16(acc[mi][ni], af[mi], bf[ni]);
        }
        __syncthreads();
    }

    // ---- epilogue ----
#pragma unroll
    for (int mi = 0; mi < MT; mi++) {
        const int row0 = bm * BM + wmBase + mi * 16 + g;
#pragma unroll
        for (int ni = 0; ni < NTI; ni++) {
            const int col = nOff + wnBase + ni * 8 + c * 2;
            float2 bb = *reinterpret_cast<const float2*>(&bias[col]);
            float2 o0, o1;
            o0.x = acc[mi][ni][0] + bb.x;
            o0.y = acc[mi][ni][1] + bb.y;
            o1.x = acc[mi][ni][2] + bb.x;
            o1.y = acc[mi][ni][3] + bb.y;
            if constexpr (RES) {
                float2 r0 = *reinterpret_cast<const float2*>(&res[(size_t)row0 * ldC + col]);
                float2 r1 = *reinterpret_cast<const float2*>(&res[(size_t)(row0 + 8) * ldC + col]);
                o0.x += r0.x; o0.y += r0.y;
                o1.x += r1.x; o1.y += r1.y;
            }
            *reinterpret_cast<float2*>(&C[(size_t)row0 * ldC + col]) = o0;
            *reinterpret_cast<float2*>(&C[(size_t)(row0 + 8) * ldC + col]) = o1;
        }
    }
}

// ---------------- sampling v4: 4 heads per warp, float4 channels, fp16 out ----------------
__global__ void __launch_bounds__(256)
sample_kernel(const float* __restrict__ refp, const float* __restrict__ oa,
              __half* __restrict__ outp)
{
    const int lane  = threadIdx.x & 31;
    const int wid   = threadIdx.x >> 5;
    const int bq    = blockIdx.x * 4 + (wid >> 1);
    const int b     = bq / NQ;
    const int hG    = (wid & 1) * 4;
    const int group = lane >> 3;
    const int h     = hG + group;
    const int ch4   = lane & 7;

    const float* oabase = oa + (size_t)bq * 96;

    float aw = 0.f, ox = 0.f, oy = 0.f;
    {
        const int hg = hG + (lane >> 2);
        const int p  = lane & 3;
        if (lane < 16) {
            aw = oabase[64 + hg * 4 + p];
            ox = oabase[hg * 8 + 2 * p];
            oy = oabase[hg * 8 + 2 * p + 1];
        }
    }
    float m = fmaxf(aw, __shfl_xor_sync(0xffffffffu, aw, 1));
    m = fmaxf(m, __shfl_xor_sync(0xffffffffu, m, 2));
    float e = __expf(aw - m);
    float s = e + __shfl_xor_sync(0xffffffffu, e, 1);
    s = s + __shfl_xor_sync(0xffffffffu, s, 2);
    const float wp = e / s;

    const float rx = refp[(size_t)bq * 2 + 0];
    const float ry = refp[(size_t)bq * 2 + 1];

    int   i00 = 0, i01 = 0, i10 = 0, i11 = 0;
    float w00 = 0.f, w01 = 0.f, w10 = 0.f, w11 = 0.f;
    {
        float locx = rx + ox * (1.f / (float)SW);
        float locy = ry + oy * (1.f / (float)SH);
        float gx = 2.f * locx - 1.f;
        float gy = 2.f * locy - 1.f;
        float px = ((gx + 1.f) * (float)SW - 1.f) * 0.5f;
        float py = ((gy + 1.f) * (float)SH - 1.f) * 0.5f;
        float x0f = floorf(px), y0f = floorf(py);
        int   x0 = (int)x0f,    y0 = (int)y0f;
        float fx = px - x0f,    fy = py - y0f;

        const bool xv0 = (x0 >= 0)     && (x0 <= SW - 1);
        const bool xv1 = (x0 + 1 >= 0) && (x0 + 1 <= SW - 1);
        const bool yv0 = (y0 >= 0)     && (y0 <= SH - 1);
        const bool yv1 = (y0 + 1 >= 0) && (y0 + 1 <= SH - 1);

        int xc0 = min(max(x0, 0), SW - 1);
        int xc1 = min(max(x0 + 1, 0), SW - 1);
        int yc0 = min(max(y0, 0), SH - 1);
        int yc1 = min(max(y0 + 1, 0), SH - 1);

        w00 = (xv0 && yv0) ? wp * (1.f - fx) * (1.f - fy) : 0.f;
        w01 = (xv1 && yv0) ? wp * fx * (1.f - fy)         : 0.f;
        w10 = (xv0 && yv1) ? wp * (1.f - fx) * fy         : 0.f;
        w11 = (xv1 && yv1) ? wp * fx * fy                 : 0.f;

        i00 = (yc0 * SW + xc0) * (EMBED / 4);
        i01 = (yc0 * SW + xc1) * (EMBED / 4);
        i10 = (yc1 * SW + xc0) * (EMBED / 4);
        i11 = (yc1 * SW + xc1) * (EMBED / 4);
    }

    const float4* vbase = reinterpret_cast<const float4*>(
        g_v + (size_t)b * NV * EMBED + h * HEAD_DIM) + ch4;

    float4 acc; acc.x = 0.f; acc.y = 0.f; acc.z = 0.f; acc.w = 0.f;
#pragma unroll
    for (int p = 0; p < POINTS; p++) {
        const int src = group * 4 + p;
        const int   j00 = __shfl_sync(0xffffffffu, i00, src);
        const int   j01 = __shfl_sync(0xffffffffu, i01, src);
        const int   j10 = __shfl_sync(0xffffffffu, i10, src);
        const int   j11 = __shfl_sync(0xffffffffu, i11, src);
        const float u00 = __shfl_sync(0xffffffffu, w00, src);
        const float u01 = __shfl_sync(0xffffffffu, w01, src);
        const float u10 = __shfl_sync(0xffffffffu, w10, src);
        const float u11 = __shfl_sync(0xffffffffu, w11, src);
        float4 v00 = vbase[j00];
        float4 v01 = vbase[j01];
        float4 v10 = vbase[j10];
        float4 v11 = vbase[j11];
        acc.x = fmaf(u00, v00.x, acc.x); acc.y = fmaf(u00, v00.y, acc.y);
        acc.z = fmaf(u00, v00.z, acc.z); acc.w = fmaf(u00, v00.w, acc.w);
        acc.x = fmaf(u01, v01.x, acc.x); acc.y = fmaf(u01, v01.y, acc.y);
        acc.z = fmaf(u01, v01.z, acc.z); acc.w = fmaf(u01, v01.w, acc.w);
        acc.x = fmaf(u10, v10.x, acc.x); acc.y = fmaf(u10, v10.y, acc.y);
        acc.z = fmaf(u10, v10.z, acc.z); acc.w = fmaf(u10, v10.w, acc.w);
        acc.x = fmaf(u11, v11.x, acc.x); acc.y = fmaf(u11, v11.y, acc.y);
        acc.z = fmaf(u11, v11.z, acc.z); acc.w = fmaf(u11, v11.w, acc.w);
    }

    uint2 pk;
    pk.x = cvt_f16x2(acc.y, acc.x);
    pk.y = cvt_f16x2(acc.w, acc.z);
    *reinterpret_cast<uint2*>(&outp[(size_t)bq * EMBED + h * HEAD_DIM + ch4 * 4]) = pk;
}

// ---------------- launch ----------------
extern "C" void kernel_launch(void* const* d_in, const int* in_sizes, int n_in,
                              void* d_out, int out_size)
{
    const float* query   = (const float*)d_in[0];
    const float* value   = (const float*)d_in[1];
    const float* refpts  = (const float*)d_in[2];
    const float* W_value = (const float*)d_in[4];
    const float* b_value = (const float*)d_in[5];
    const float* W_off   = (const float*)d_in[6];
    const float* b_off   = (const float*)d_in[7];
    const float* W_attn  = (const float*)d_in[8];
    const float* b_attn  = (const float*)d_in[9];
    const float* W_out   = (const float*)d_in[10];
    const float* b_out   = (const float*)d_in[11];
    float* out = (float*)d_out;

    float *pv, *poa, *pboa;
    __half *ptmp, *wv, *wo, *woa;
    cudaGetSymbolAddress((void**)&pv,   g_v);
    cudaGetSymbolAddress((void**)&poa,  g_oa);
    cudaGetSymbolAddress((void**)&ptmp, g_tmp);
    cudaGetSymbolAddress((void**)&pboa, g_boa);
    cudaGetSymbolAddress((void**)&wv,   g_Wv);
    cudaGetSymbolAddress((void**)&wo,   g_Wo);
    cudaGetSymbolAddress((void**)&woa,  g_Woa);

    const int SMEM_128 = (64 + 128) * 272; // 52224
    const int SMEM_96  = (64 +  96) * 272; // 43520
    cudaFuncSetAttribute(mma_gemm_kernel<128, false, float >, cudaFuncAttributeMaxDynamicSharedMemorySize, SMEM_128);
    cudaFuncSetAttribute(mma_gemm_kernel<128, true,  __half>, cudaFuncAttributeMaxDynamicSharedMemorySize, SMEM_128);
    cudaFuncSetAttribute(mma_gemm_kernel< 96, false, float >, cudaFuncAttributeMaxDynamicSharedMemorySize, SMEM_96);

    // merged weight transpose to fp16
    convert_all_kernel<<<(131072 + 24576 + 255) / 256, 256>>>(
        W_value, W_out, W_off, b_off, W_attn, b_attn, wv, wo, woa, pboa);

    const int GRID_M = MROWS / 64; // 1250

    // 1) v = value @ W_value + b_value
    mma_gemm_kernel<128, false, float><<<dim3(2, GRID_M), 256, SMEM_128>>>(
        value, wv, b_value, nullptr, pv, 256);
    // 2+3) [off|attn] = query @ [W_off|W_attn] + bias
    mma_gemm_kernel<96, false, float><<<dim3(1, GRID_M), 256, SMEM_96>>>(
        query, woa, pboa, nullptr, poa, 96);
    // 4) softmax + bilinear sample -> fp16 tmp
    sample_kernel<<<MROWS / 4, 256>>>(refpts, poa, ptmp);
    // 5) out = tmp(fp16) @ W_out + b_out + query
    mma_gemm_kernel<128, true, __half><<<dim3(2, GRID_M), 256, SMEM_128>>>(
        ptmp, wo, b_out, query, out, 256);
}

// round 16
// speedup vs baseline: 1.1871x; 1.1871x over previous
#include <cuda_runtime.h>
#include <cuda_fp16.h>
#include <math.h>
#include <stdint.h>

// ---------------- problem constants ----------------
#define BS      2
#define NQ      40000
#define NV      40000
#define EMBED   256
#define HEADS   8
#define POINTS  4
#define HEAD_DIM 32
#define SH      200
#define SW      200
#define MROWS   (BS * NQ)      // 80000

// ---------------- device scratch ----------------
__device__ __half g_v   [(size_t)BS * NV * EMBED];       // projected value (fp16)
__device__ float  g_oa  [(size_t)BS * NQ * 96];          // fused [off(64) | attn(32)]
__device__ __half g_tmp [(size_t)BS * NQ * EMBED];       // sampled output (fp16)
__device__ float  g_boa [96];
// transposed weights: [N][K] fp16
__device__ __half g_Wv [256 * 256];
__device__ __half g_Wo [256 * 256];
__device__ __half g_Woa[ 96 * 256];

// ---------------- warp mma / ldmatrix helpers ----------------
__device__ __forceinline__ void mma_f16(float* d, const uint32_t* a, const uint32_t* b) {
    asm volatile(
        "mma.sync.aligned.m16n8k16.row.col.f32.f16.f16.f32 "
        "{%0,%1,%2,%3}, {%4,%5,%6,%7}, {%8,%9}, {%0,%1,%2,%3};"
        : "+f"(d[0]), "+f"(d[1]), "+f"(d[2]), "+f"(d[3])
        : "r"(a[0]), "r"(a[1]), "r"(a[2]), "r"(a[3]), "r"(b[0]), "r"(b[1]));
}
__device__ __forceinline__ void ldsm_x4(uint32_t& r0, uint32_t& r1, uint32_t& r2, uint32_t& r3,
                                        uint32_t addr) {
    asm volatile("ldmatrix.sync.aligned.m8n8.x4.shared.b16 {%0,%1,%2,%3}, [%4];"
                 : "=r"(r0), "=r"(r1), "=r"(r2), "=r"(r3) : "r"(addr));
}
__device__ __forceinline__ void ldsm_x2(uint32_t& r0, uint32_t& r1, uint32_t addr) {
    asm volatile("ldmatrix.sync.aligned.m8n8.x2.shared.b16 {%0,%1}, [%2];"
                 : "=r"(r0), "=r"(r1) : "r"(addr));
}
__device__ __forceinline__ uint32_t cvt_f16x2(float hi, float lo) {
    uint32_t r;
    asm("cvt.rn.f16x2.f32 %0, %1, %2;" : "=r"(r) : "f"(hi), "f"(lo));
    return r;
}

// ---------------- merged weight transpose to fp16 ----------------
__global__ void convert_all_kernel(const float* __restrict__ Wv, const float* __restrict__ Wo,
                                   const float* __restrict__ Woff, const float* __restrict__ boff,
                                   const float* __restrict__ Wattn, const float* __restrict__ battn,
                                   __half* __restrict__ dWv, __half* __restrict__ dWo,
                                   __half* __restrict__ dWoa, float* __restrict__ bcomb)
{
    int idx = blockIdx.x * 256 + threadIdx.x;
    if (idx < 65536) {
        int n = idx >> 8, k = idx & 255;
        dWv[idx] = __float2half_rn(Wv[k * 256 + n]);
    } else if (idx < 131072) {
        int j = idx - 65536;
        int n = j >> 8, k = j & 255;
        dWo[j] = __float2half_rn(Wo[k * 256 + n]);
    } else if (idx < 131072 + 24576) {
        int j = idx - 131072;
        int n = j >> 8, k = j & 255;
        float v = (n < 64) ? Woff[k * 64 + n] : Wattn[k * 32 + (n - 64)];
        dWoa[j] = __float2half_rn(v);
        if (j < 96) bcomb[j] = (j < 64) ? boff[j] : battn[j - 64];
    }
}

// ---------------- fp16 HMMA GEMM: single pass, BM=128, BK=128 (round-12 proven) ----------
// AT = float (cvt fill) or __half (copy fill). OT = float or __half output.
template<int BN, bool RES, typename AT, typename OT>
__global__ void __launch_bounds__(256, 2)
mma_gemm_kernel(const AT* __restrict__ A,
                const __half* __restrict__ Bt,
                const float* __restrict__ bias,
                const float* __restrict__ res,
                OT* __restrict__ C, int ldC)
{
    constexpr int K = 256, BK = 128, BM = 128;
    constexpr int WN  = 4;
    constexpr int WTN = BN / WN;
    constexpr int MT  = 4;
    constexpr int NTI = WTN / 8;
    constexpr int NPAIR = NTI / 2;
    constexpr int AST = 272;               // bytes per 128-fp16 row (256 + 16 pad)
    constexpr int A_0 = 0;
    constexpr int B_0 = BM * AST;

    extern __shared__ char sm[];
    const uint32_t smBase = (uint32_t)__cvta_generic_to_shared(sm);

    const int tid  = threadIdx.x;
    const int wid  = tid >> 5;
    const int lane = tid & 31;
    const int g    = lane >> 2;
    const int c    = lane & 3;
    const int wm   = wid / WN;
    const int wn   = wid % WN;
    const int wmBase = wm * 64;
    const int wnBase = wn * WTN;
    const int bm   = blockIdx.y;
    const int nOff = blockIdx.x * BN;

    float acc[MT][NTI][4];
#pragma unroll
    for (int i = 0; i < MT; i++)
#pragma unroll
        for (int j = 0; j < NTI; j++)
#pragma unroll
            for (int q = 0; q < 4; q++) acc[i][j][q] = 0.f;

    const int aRow = wmBase + (lane & 15);
    const int aKs  = (lane >> 4) * 16;
    const int bRow = wnBase + ((lane >> 4) << 3) + (lane & 7);
    const int bKs  = ((lane >> 3) & 1) * 16;
    const uint32_t aB = smBase + (uint32_t)(A_0 + aRow * AST + aKs);
    const uint32_t bB = smBase + (uint32_t)(B_0 + bRow * AST + bKs);

    for (int it = 0; it < K / BK; it++) {
        const int k0 = it * BK;
        if constexpr (sizeof(AT) == 4) {
#pragma unroll
            for (int f = tid; f < BM * 32; f += 256) {
                const int r = f >> 5, c4 = f & 31;
                float4 a = *reinterpret_cast<const float4*>(
                    &A[(size_t)(bm * BM + r) * K + k0 + c4 * 4]);
                uint2 v;
                v.x = cvt_f16x2(a.y, a.x);
                v.y = cvt_f16x2(a.w, a.z);
                *reinterpret_cast<uint2*>(sm + A_0 + r * AST + c4 * 8) = v;
            }
        } else {
#pragma unroll
            for (int f = tid; f < BM * 16; f += 256) {
                const int r = f >> 4, cu = f & 15;
                uint4 w = *reinterpret_cast<const uint4*>(
                    &A[(size_t)(bm * BM + r) * K + k0 + cu * 8]);
                *reinterpret_cast<uint4*>(sm + A_0 + r * AST + cu * 16) = w;
            }
        }
#pragma unroll
        for (int f = tid; f < BN * 16; f += 256) {
            const int n = f >> 4, cu = f & 15;
            uint4 w = *reinterpret_cast<const uint4*>(&Bt[(nOff + n) * K + k0 + cu * 8]);
            *reinterpret_cast<uint4*>(sm + B_0 + n * AST + cu * 16) = w;
        }
        __syncthreads();

#pragma unroll
        for (int ks = 0; ks < BK / 16; ks++) {
            const uint32_t kb = ks * 32;
            uint32_t af[MT][4], bf[NTI][2];
#pragma unroll
            for (int p = 0; p < NPAIR; p++)
                ldsm_x4(bf[2*p][0], bf[2*p][1], bf[2*p+1][0], bf[2*p+1][1],
                        bB + (uint32_t)(p * 16 * AST) + kb);
            if (NTI & 1)
                ldsm_x2(bf[NTI-1][0], bf[NTI-1][1],
                        bB + (uint32_t)((NTI-1) * 8 * AST) + kb);
#pragma unroll
            for (int mi = 0; mi < MT; mi++)
                ldsm_x4(af[mi][0], af[mi][1], af[mi][2], af[mi][3],
                        aB + (uint32_t)(mi * 16 * AST) + kb);
#pragma unroll
            for (int mi = 0; mi < MT; mi++)
#pragma unroll
                for (int ni = 0; ni < NTI; ni++)
                    mma_f16(acc[mi][ni], af[mi], bf[ni]);
        }
        __syncthreads();
    }

    // ---- epilogue ----
#pragma unroll
    for (int mi = 0; mi < MT; mi++) {
        const int row0 = bm * BM + wmBase + mi * 16 + g;
#pragma unroll
        for (int ni = 0; ni < NTI; ni++) {
            const int col = nOff + wnBase + ni * 8 + c * 2;
            float2 bb = *reinterpret_cast<const float2*>(&bias[col]);
            float2 o0, o1;
            o0.x = acc[mi][ni][0] + bb.x;
            o0.y = acc[mi][ni][1] + bb.y;
            o1.x = acc[mi][ni][2] + bb.x;
            o1.y = acc[mi][ni][3] + bb.y;
            if constexpr (RES) {
                float2 r0 = *reinterpret_cast<const float2*>(&res[(size_t)row0 * ldC + col]);
                float2 r1 = *reinterpret_cast<const float2*>(&res[(size_t)(row0 + 8) * ldC + col]);
                o0.x += r0.x; o0.y += r0.y;
                o1.x += r1.x; o1.y += r1.y;
            }
            if constexpr (sizeof(OT) == 2) {
                uint32_t p0 = cvt_f16x2(o0.y, o0.x);
                uint32_t p1 = cvt_f16x2(o1.y, o1.x);
                *reinterpret_cast<uint32_t*>(&C[(size_t)row0 * ldC + col]) = p0;
                *reinterpret_cast<uint32_t*>(&C[(size_t)(row0 + 8) * ldC + col]) = p1;
            } else {
                *reinterpret_cast<float2*>(&C[(size_t)row0 * ldC + col]) = o0;
                *reinterpret_cast<float2*>(&C[(size_t)(row0 + 8) * ldC + col]) = o1;
            }
        }
    }
}

// ---------------- sampling v6: 4 heads per warp, fp16 v, uint2 (4-half) gathers ----------
// Head rows are 64B; heads (0,1) and (2,3) share 128B lines -> 2 lines per gather instr.
__global__ void __launch_bounds__(256)
sample_kernel(const float* __restrict__ refp, const float* __restrict__ oa,
              __half* __restrict__ outp)
{
    const int lane  = threadIdx.x & 31;
    const int wid   = threadIdx.x >> 5;
    const int bq    = blockIdx.x * 4 + (wid >> 1);
    const int b     = bq / NQ;
    const int hG    = (wid & 1) * 4;
    const int group = lane >> 3;            // 0..3 -> head hG+group
    const int h     = hG + group;
    const int ch4   = lane & 7;             // 4-half chunk index within head

    const float* oabase = oa + (size_t)bq * 96;

    float aw = 0.f, ox = 0.f, oy = 0.f;
    {
        const int hg = hG + (lane >> 2);
        const int p  = lane & 3;
        if (lane < 16) {
            aw = oabase[64 + hg * 4 + p];
            ox = oabase[hg * 8 + 2 * p];
            oy = oabase[hg * 8 + 2 * p + 1];
        }
    }
    float m = fmaxf(aw, __shfl_xor_sync(0xffffffffu, aw, 1));
    m = fmaxf(m, __shfl_xor_sync(0xffffffffu, m, 2));
    float e = __expf(aw - m);
    float s = e + __shfl_xor_sync(0xffffffffu, e, 1);
    s = s + __shfl_xor_sync(0xffffffffu, s, 2);
    const float wp = e / s;

    const float rx = refp[(size_t)bq * 2 + 0];
    const float ry = refp[(size_t)bq * 2 + 1];

    int   i00 = 0, i01 = 0, i10 = 0, i11 = 0;   // uint2-unit offsets (pos * 64)
    float w00 = 0.f, w01 = 0.f, w10 = 0.f, w11 = 0.f;
    {
        float locx = rx + ox * (1.f / (float)SW);
        float locy = ry + oy * (1.f / (float)SH);
        float gx = 2.f * locx - 1.f;
        float gy = 2.f * locy - 1.f;
        float px = ((gx + 1.f) * (float)SW - 1.f) * 0.5f;
        float py = ((gy + 1.f) * (float)SH - 1.f) * 0.5f;
        float x0f = floorf(px), y0f = floorf(py);
        int   x0 = (int)x0f,    y0 = (int)y0f;
        float fx = px - x0f,    fy = py - y0f;

        const bool xv0 = (x0 >= 0)     && (x0 <= SW - 1);
        const bool xv1 = (x0 + 1 >= 0) && (x0 + 1 <= SW - 1);
        const bool yv0 = (y0 >= 0)     && (y0 <= SH - 1);
        const bool yv1 = (y0 + 1 >= 0) && (y0 + 1 <= SH - 1);

        int xc0 = min(max(x0, 0), SW - 1);
        int xc1 = min(max(x0 + 1, 0), SW - 1);
        int yc0 = min(max(y0, 0), SH - 1);
        int yc1 = min(max(y0 + 1, 0), SH - 1);

        w00 = (xv0 && yv0) ? wp * (1.f - fx) * (1.f - fy) : 0.f;
        w01 = (xv1 && yv0) ? wp * fx * (1.f - fy)         : 0.f;
        w10 = (xv0 && yv1) ? wp * (1.f - fx) * fy         : 0.f;
        w11 = (xv1 && yv1) ? wp * fx * fy                 : 0.f;

        i00 = (yc0 * SW + xc0) * (EMBED / 4);
        i01 = (yc0 * SW + xc1) * (EMBED / 4);
        i10 = (yc1 * SW + xc0) * (EMBED / 4);
        i11 = (yc1 * SW + xc1) * (EMBED / 4);
    }

    const uint2* vbase = reinterpret_cast<const uint2*>(
        g_v + (size_t)b * NV * EMBED + h * HEAD_DIM) + ch4;

    float4 acc; acc.x = 0.f; acc.y = 0.f; acc.z = 0.f; acc.w = 0.f;
#pragma unroll
    for (int p = 0; p < POINTS; p++) {
        const int src = group * 4 + p;
        const int   j00 = __shfl_sync(0xffffffffu, i00, src);
        const int   j01 = __shfl_sync(0xffffffffu, i01, src);
        const int   j10 = __shfl_sync(0xffffffffu, i10, src);
        const int   j11 = __shfl_sync(0xffffffffu, i11, src);
        const float u00 = __shfl_sync(0xffffffffu, w00, src);
        const float u01 = __shfl_sync(0xffffffffu, w01, src);
        const float u10 = __shfl_sync(0xffffffffu, w10, src);
        const float u11 = __shfl_sync(0xffffffffu, w11, src);
        uint2 r00 = vbase[j00];
        uint2 r01 = vbase[j01];
        uint2 r10 = vbase[j10];
        uint2 r11 = vbase[j11];
        float2 a0 = __half22float2(*reinterpret_cast<__half2*>(&r00.x));
        float2 a1 = __half22float2(*reinterpret_cast<__half2*>(&r00.y));
        acc.x = fmaf(u00, a0.x, acc.x); acc.y = fmaf(u00, a0.y, acc.y);
        acc.z = fmaf(u00, a1.x, acc.z); acc.w = fmaf(u00, a1.y, acc.w);
        a0 = __half22float2(*reinterpret_cast<__half2*>(&r01.x));
        a1 = __half22float2(*reinterpret_cast<__half2*>(&r01.y));
        acc.x = fmaf(u01, a0.x, acc.x); acc.y = fmaf(u01, a0.y, acc.y);
        acc.z = fmaf(u01, a1.x, acc.z); acc.w = fmaf(u01, a1.y, acc.w);
        a0 = __half22float2(*reinterpret_cast<__half2*>(&r10.x));
        a1 = __half22float2(*reinterpret_cast<__half2*>(&r10.y));
        acc.x = fmaf(u10, a0.x, acc.x); acc.y = fmaf(u10, a0.y, acc.y);
        acc.z = fmaf(u10, a1.x, acc.z); acc.w = fmaf(u10, a1.y, acc.w);
        a0 = __half22float2(*reinterpret_cast<__half2*>(&r11.x));
        a1 = __half22float2(*reinterpret_cast<__half2*>(&r11.y));
        acc.x = fmaf(u11, a0.x, acc.x); acc.y = fmaf(u11, a0.y, acc.y);
        acc.z = fmaf(u11, a1.x, acc.z); acc.w = fmaf(u11, a1.y, acc.w);
    }

    uint2 pk;
    pk.x = cvt_f16x2(acc.y, acc.x);
    pk.y = cvt_f16x2(acc.w, acc.z);
    *reinterpret_cast<uint2*>(&outp[(size_t)bq * EMBED + h * HEAD_DIM + ch4 * 4]) = pk;
}

// ---------------- launch ----------------
extern "C" void kernel_launch(void* const* d_in, const int* in_sizes, int n_in,
                              void* d_out, int out_size)
{
    const float* query   = (const float*)d_in[0];
    const float* value   = (const float*)d_in[1];
    const float* refpts  = (const float*)d_in[2];
    const float* W_value = (const float*)d_in[4];
    const float* b_value = (const float*)d_in[5];
    const float* W_off   = (const float*)d_in[6];
    const float* b_off   = (const float*)d_in[7];
    const float* W_attn  = (const float*)d_in[8];
    const float* b_attn  = (const float*)d_in[9];
    const float* W_out   = (const float*)d_in[10];
    const float* b_out   = (const float*)d_in[11];
    float* out = (float*)d_out;

    float *poa, *pboa;
    __half *pv, *ptmp, *wv, *wo, *woa;
    cudaGetSymbolAddress((void**)&pv,   g_v);
    cudaGetSymbolAddress((void**)&poa,  g_oa);
    cudaGetSymbolAddress((void**)&ptmp, g_tmp);
    cudaGetSymbolAddress((void**)&pboa, g_boa);
    cudaGetSymbolAddress((void**)&wv,   g_Wv);
    cudaGetSymbolAddress((void**)&wo,   g_Wo);
    cudaGetSymbolAddress((void**)&woa,  g_Woa);

    const int SMEM_128 = (128 + 128) * 272; // 69632
    const int SMEM_96  = (128 +  96) * 272; // 60928
    cudaFuncSetAttribute((const void*)mma_gemm_kernel<128, false, float, __half>,
                         cudaFuncAttributeMaxDynamicSharedMemorySize, SMEM_128);
    cudaFuncSetAttribute((const void*)mma_gemm_kernel<128, true, __half, float>,
                         cudaFuncAttributeMaxDynamicSharedMemorySize, SMEM_128);
    cudaFuncSetAttribute((const void*)mma_gemm_kernel<96, false, float, float>,
                         cudaFuncAttributeMaxDynamicSharedMemorySize, SMEM_96);

    // merged weight transpose to fp16
    convert_all_kernel<<<(131072 + 24576 + 255) / 256, 256>>>(
        W_value, W_out, W_off, b_off, W_attn, b_attn, wv, wo, woa, pboa);

    const int GRID = MROWS / 128; // 625

    // 1) v = value @ W_value + b_value -> fp16   (N split fast-dim)
    mma_gemm_kernel<128, false, float, __half><<<dim3(2, GRID), 256, SMEM_128>>>(
        value, wv, b_value, nullptr, pv, 256);
    // 2+3) [off|attn] = query @ [W_off|W_attn] + bias   (N=96)
    mma_gemm_kernel<96, false, float, float><<<dim3(1, GRID), 256, SMEM_96>>>(
        query, woa, pboa, nullptr, poa, 96);
    // 4) softmax + bilinear sample (fp16 v, line-sharing gathers) -> fp16 tmp
    sample_kernel<<<MROWS / 4, 256>>>(refpts, poa, ptmp);
    // 5) out = tmp(fp16) @ W_out + b_out + query
    mma_gemm_kernel<128, true, __half, float><<<dim3(2, GRID), 256, SMEM_128>>>(
        ptmp, wo, b_out, query, out, 256);
}